// round 7
// baseline (speedup 1.0000x reference)
#include <cuda_runtime.h>
#include <cuda_fp16.h>
#include <math.h>
#include <stdint.h>

#define BB   2
#define CIN  16
#define NG   6
#define CG   16
#define NOC  96
#define TT   31
#define HH   128
#define WW   128
#define HWSZ (HH*WW)

// CTA pixel tile: 16h x 16w = 256 px
#define PH   16
#define PW   16
#define NTHR 384            // 12 warps: 4 m-tiles (4h x 16w) x 3 n-tiles (32oc)

// smem:
//   xt [3][18][18][24]  at 0       : 46656 B   (halves, CIP=24 stride)
//   B9 [9][96][24]      at 46656   : 41472 B
#define CIP      24
#define XT_BYTES (3*18*18*CIP*2)
#define B9_OFF   XT_BYTES
#define B9_BYTES (9*NOC*CIP*2)
#define SMEM_DYN (XT_BYTES + B9_BYTES)   // 88128

#define RS  (CIP*2)   // 48B row stride

// gates scratch [g][b][c][t][h][w]
__device__ float g_gates[(size_t)NG * BB * CG * TT * HWSZ];
// fp16 weights [j=27][oc=96][ci=16]
__device__ __align__(16) __half g_wH[27 * NOC * CIN];

// ---------------- helpers ----------------
__device__ __forceinline__ uint32_t smem_u32(const void* p) {
    uint32_t a;
    asm("{ .reg .u64 t; cvta.to.shared.u64 t, %1; cvt.u32.u64 %0, t; }"
        : "=r"(a) : "l"(p));
    return a;
}
__device__ __forceinline__ float ex2f(float z) {
    float r; asm("ex2.approx.f32 %0, %1;" : "=f"(r) : "f"(z)); return r;
}
__device__ __forceinline__ float rcpn(float d) {
    float r; asm("rcp.approx.f32 %0, %1;" : "=f"(r) : "f"(d));
    return r * fmaf(-d, r, 2.0f);
}
__device__ __forceinline__ float sigf(float v) {
    v = fminf(fmaxf(v, -80.f), 80.f);
    return rcpn(1.0f + ex2f(-1.442695041f * v));
}
__device__ __forceinline__ float tanhfst(float v) {
    v = fminf(fmaxf(v, -40.f), 40.f);
    return fmaf(2.0f, rcpn(1.0f + ex2f(-2.885390082f * v)), -1.0f);
}

#define MMA_F16(c, a0, a1, a2, a3, b0, b1)                                    \
    asm volatile("mma.sync.aligned.m16n8k16.row.col.f32.f16.f16.f32 "         \
                 "{%0,%1,%2,%3}, {%4,%5,%6,%7}, {%8,%9}, {%0,%1,%2,%3};"      \
                 : "+f"((c)[0]), "+f"((c)[1]), "+f"((c)[2]), "+f"((c)[3])     \
                 : "r"(a0), "r"(a1), "r"(a2), "r"(a3), "r"(b0), "r"(b1))

#define LDSM_X4(r0, r1, r2, r3, addr)                                         \
    asm volatile("ldmatrix.sync.aligned.m8n8.x4.shared.b16 {%0,%1,%2,%3}, [%4];" \
                 : "=r"(r0), "=r"(r1), "=r"(r2), "=r"(r3) : "r"(addr))

// ---------------- weight prep: [oc][ci][j] f32 -> [j][oc][ci] f16 ----------
__global__ void prep_w(const float* __restrict__ cw)
{
    int i = blockIdx.x * 256 + threadIdx.x;           // [0, 27*96*16)
    if (i >= 27 * NOC * CIN) return;
    int ci = i % CIN;
    int oc = (i / CIN) % NOC;
    int j  = i / (CIN * NOC);
    g_wH[i] = __float2half_rn(cw[(oc * CIN + ci) * 27 + j]);
}

// ---------------- conv via mma.sync fp16 + ldmatrix ----------------
__global__ __launch_bounds__(NTHR)
void conv_mma(const float* __restrict__ x, const float* __restrict__ cb)
{
    extern __shared__ __align__(16) char dsm[];
    __shared__ float cbs[NOC];

    const int tid = threadIdx.x;
    const int wid = tid >> 5;
    const int lid = tid & 31;
    const int wm  = wid & 3;          // m-tile: 4 h-rows x 16 w
    const int wn  = wid >> 2;         // n-tile: 32 oc, 0..2

    const int w0 = blockIdx.x * PW;
    const int h0 = blockIdx.y * PH;
    const int zz = blockIdx.z;
    const int t = zz % TT, b = zz / TT;

    const uint32_t sbase = smem_u32(dsm);

    if (tid < NOC) cbs[tid] = __ldg(&cb[tid]);

    // ---- stage xt[3][18][18][24] halves (zero-padded halo) ----
    {
        const float* xb = x + (size_t)b * CIN * TT * HWSZ;
        for (int i = tid; i < 3 * CIN * 18 * 18; i += NTHR) {
            int iw = i % 18;
            int ih = (i / 18) % 18;
            int ci = (i / 324) % CIN;
            int dt = i / (324 * CIN);
            int tg = t - 1 + dt, hh = h0 - 1 + ih, ww = w0 - 1 + iw;
            float v = 0.0f;
            if ((unsigned)tg < TT && (unsigned)hh < HH && (unsigned)ww < WW)
                v = xb[((size_t)ci * TT + tg) * HWSZ + hh * WW + ww];
            *(__half*)(dsm + (((dt * 18 + ih) * 18 + iw) * CIP + ci) * 2)
                = __float2half_rn(v);
        }
    }

    // ---- C fragments init with bias ----
    float c[4][4][4];
    {
        const int ocb = wn * 32 + (lid & 3) * 2;
#pragma unroll
        for (int mb = 0; mb < 4; mb++)
#pragma unroll
            for (int nf = 0; nf < 4; nf++) {
                float b0v = cbs[ocb + nf * 8];
                float b1v = cbs[ocb + nf * 8 + 1];
                c[mb][nf][0] = b0v; c[mb][nf][1] = b1v;
                c[mb][nf][2] = b0v; c[mb][nf][3] = b1v;
            }
    }

    // ldmatrix lane address components
    // A x4: tiles (m0-7,k0-7)(m8-15,k0-7)(m0-7,k8-15)(m8-15,k8-15)
    const int aRow  = (lid & 7) + 8 * ((lid >> 3) & 1);   // w-pixel within tile
    const int aKoff = ((lid >> 4) & 1) * 16;              // k byte offset
    const uint32_t laneA = sbase + (uint32_t)(aRow * RS + aKoff);
    // B x4: n = lid (tiles n0-7..n24-31, fixed k-block)
    const uint32_t laneB = sbase + B9_OFF + (uint32_t)((wn * 32 + lid) * RS);
    const int hrow = wm * 4;

    for (int dt = 0; dt < 3; dt++) {
        __syncthreads();   // xt staged (dt=0) / prev B9 consumers done
        // stage B9[9][96][24] halves for this dt
        {
            const float4* src = (const float4*)g_wH;
            for (int i = tid; i < 9 * NOC * 2; i += NTHR) {
                int rr = i >> 1;                 // j9*96 + oc
                int q  = i & 1;
                float4 v = src[(dt * 9 * NOC + rr) * 2 + q];
                *(float4*)(dsm + B9_OFF + rr * RS + q * 16) = v;
            }
        }
        __syncthreads();

#pragma unroll
        for (int dh = 0; dh < 3; dh++)
#pragma unroll
            for (int dw = 0; dw < 3; dw++) {
                const int j9 = dh * 3 + dw;
                // B fragments: 2 x LDSM.x4 (k-block 0 and 1)
                uint32_t b0[4], b1[4];
                {
                    uint32_t ba = laneB + (uint32_t)(j9 * NOC * RS);
                    LDSM_X4(b0[0], b0[1], b0[2], b0[3], ba);
                    LDSM_X4(b1[0], b1[1], b1[2], b1[3], ba + 16u);
                }
#pragma unroll
                for (int mb = 0; mb < 4; mb++) {
                    uint32_t aa = laneA + (uint32_t)
                        ((((dt * 18 + hrow + mb + dh) * 18 + dw)) * RS);
                    uint32_t a0, a1, a2, a3;
                    LDSM_X4(a0, a1, a2, a3, aa);
#pragma unroll
                    for (int nf = 0; nf < 4; nf++)
                        MMA_F16(c[mb][nf], a0, a1, a2, a3, b0[nf], b1[nf]);
                }
            }
    }

    // ---- epilogue: activate + direct store ----
    {
        const int r  = lid >> 2;
        const int wA = w0 + r;
        const size_t tbase = (size_t)t * HWSZ;
#pragma unroll
        for (int mb = 0; mb < 4; mb++) {
            const int hA = h0 + hrow + mb;
            const size_t rowoff = tbase + (size_t)hA * WW;
#pragma unroll
            for (int nf = 0; nf < 4; nf++) {
                const int oc0 = wn * 32 + nf * 8 + (lid & 3) * 2;
                const int g = oc0 >> 4;
                const bool th = (g == 0) || (g == 5);
                float v0 = c[mb][nf][0], v1 = c[mb][nf][1];
                float v2 = c[mb][nf][2], v3 = c[mb][nf][3];
                v0 = th ? tanhfst(v0) : sigf(v0);
                v1 = th ? tanhfst(v1) : sigf(v1);
                v2 = th ? tanhfst(v2) : sigf(v2);
                v3 = th ? tanhfst(v3) : sigf(v3);
                float* p0 = g_gates + ((size_t)(g * BB + b) * CG + (oc0 & 15))
                            * (TT * HWSZ) + rowoff + wA;
                float* p1 = g_gates + ((size_t)(g * BB + b) * CG + ((oc0 + 1) & 15))
                            * (TT * HWSZ) + rowoff + wA;
                p0[0] = v0;  p1[0] = v1;
                p0[8] = v2;  p1[8] = v3;
            }
        }
    }
}

// ---------------- SRU scan (HBM-bound @80%, unchanged) ----------------
__global__ __launch_bounds__(256)
void sru_scan_kernel(float* __restrict__ out)
{
    const int tid = blockIdx.x * blockDim.x + threadIdx.x;
    const int hw = tid & (HWSZ - 1);
    const int bc = tid >> 14;
    const int c  = bc & 15;
    const int b  = bc >> 4;

    const size_t GSZ  = (size_t)BB * CG * TT * HWSZ;
    const size_t base = (((size_t)b * CG + c) * TT) * HWSZ + hw;

    const float* WX  = g_gates + 0 * GSZ + base;
    const float* FT  = g_gates + 1 * GSZ + base;
    const float* FT2 = g_gates + 2 * GSZ + base;
    const float* RT  = g_gates + 3 * GSZ + base;
    const float* RT2 = g_gates + 4 * GSZ + base;
    const float* XX  = g_gates + 5 * GSZ + base;
    float* o = out + base;

    float htl[TT];
    {
        float f = FT[0];
        float C = 1.0f - f;
        float r = RT[0];
        htl[0] = r * C + (1.0f - r) * XX[0];
#pragma unroll
        for (int t = 1; t < TT; t++) {
            size_t idx = (size_t)t * HWSZ;
            f = FT[idx];
            C = f * C + (1.0f - f) * WX[idx];
            float r2 = RT[idx];
            htl[t] = r2 * C + (1.0f - r2) * XX[idx];
        }
    }
    {
        size_t idx = (size_t)(TT - 1) * HWSZ;
        float f = FT2[idx];
        float C = 1.0f - f;
        float r = RT2[idx];
        o[idx] = htl[TT - 1] + r * C + (1.0f - r) * XX[idx];
#pragma unroll
        for (int t = TT - 2; t >= 0; t--) {
            idx = (size_t)t * HWSZ;
            f = FT2[idx];
            C = f * C + (1.0f - f) * WX[idx];
            float r2 = RT2[idx];
            o[idx] = htl[t] + r2 * C + (1.0f - r2) * XX[idx];
        }
    }
}

extern "C" void kernel_launch(void* const* d_in, const int* in_sizes, int n_in,
                              void* d_out, int out_size)
{
    const float* x  = (const float*)d_in[0];   // [2,16,31,128,128]
    const float* cw = (const float*)d_in[1];   // [96,16,3,3,3]
    const float* cb = (const float*)d_in[2];   // [96]
    float* out = (float*)d_out;

    cudaFuncSetAttribute(conv_mma, cudaFuncAttributeMaxDynamicSharedMemorySize,
                         SMEM_DYN);

    prep_w<<<(27 * NOC * CIN + 255) / 256, 256>>>(cw);

    dim3 grd(WW / PW, HH / PH, BB * TT);       // (8, 8, 62) = 3968 CTAs
    conv_mma<<<grd, NTHR, SMEM_DYN>>>(x, cb);

    int n = BB * CG * HWSZ;
    sru_scan_kernel<<<n / 256, 256>>>(out);
}